// round 11
// baseline (speedup 1.0000x reference)
#include <cuda_runtime.h>
#include <cuda_bf16.h>
#include <cstdint>
#include <math.h>

#define BSZ 2
#define SEQ 2048
#define DMODEL 1024
#define NHEAD 16
#define HDIM 64
#define MROWS (BSZ*SEQ)   // 4096

// Scratch (allowed: __device__ globals, no runtime alloc)
__device__ float g_Q[BSZ*NHEAD*SEQ*HDIM];   // [b][h][n][dd]
__device__ float g_K[BSZ*NHEAD*SEQ*HDIM];
__device__ float g_V[BSZ*NHEAD*SEQ*HDIM];
__device__ float g_Cc[MROWS*DMODEL];        // concat [b*n][h*64+dd]
// pre-split bf16 hi/lo operands, stored as uint4 (16B-aligned by type).
// 1 uint4 = 8 bf16 elements.
__device__ uint4 g_XH4[MROWS*DMODEL/8],  g_XL4[MROWS*DMODEL/8];
__device__ uint4 g_WH4[4*DMODEL*DMODEL/8], g_WL4[4*DMODEL*DMODEL/8];
__device__ uint4 g_CH4[MROWS*DMODEL/8],  g_CL4[MROWS*DMODEL/8];

// ---------------------------------------------------------------------------
// helpers (portable PTX on plain compute_103 target)
// ---------------------------------------------------------------------------
__device__ __forceinline__ uint32_t ph2(float lo, float hi) {
    uint32_t r;
    asm("cvt.rn.f16x2.f32 %0, %1, %2;" : "=r"(r) : "f"(hi), "f"(lo));
    return r;
}
__device__ __forceinline__ void mma_bf16(float* d, const uint32_t* a,
                                         uint32_t b0, uint32_t b1) {
    asm volatile(
        "mma.sync.aligned.m16n8k16.row.col.f32.bf16.bf16.f32 "
        "{%0,%1,%2,%3}, {%4,%5,%6,%7}, {%8,%9}, {%0,%1,%2,%3};"
        : "+f"(d[0]), "+f"(d[1]), "+f"(d[2]), "+f"(d[3])
        : "r"(a[0]), "r"(a[1]), "r"(a[2]), "r"(a[3]), "r"(b0), "r"(b1));
}
__device__ __forceinline__ void mma_f16(float* d, const uint32_t* a,
                                        uint32_t b0, uint32_t b1) {
    asm volatile(
        "mma.sync.aligned.m16n8k16.row.col.f32.f16.f16.f32 "
        "{%0,%1,%2,%3}, {%4,%5,%6,%7}, {%8,%9}, {%0,%1,%2,%3};"
        : "+f"(d[0]), "+f"(d[1]), "+f"(d[2]), "+f"(d[3])
        : "r"(a[0]), "r"(a[1]), "r"(a[2]), "r"(a[3]), "r"(b0), "r"(b1));
}
__device__ __forceinline__ void ldm4(uint32_t* r, uint32_t addr) {
    asm volatile(
        "ldmatrix.sync.aligned.m8n8.x4.shared.b16 {%0,%1,%2,%3}, [%4];"
        : "=r"(r[0]), "=r"(r[1]), "=r"(r[2]), "=r"(r[3]) : "r"(addr));
}
__device__ __forceinline__ uint32_t smem_u32(const void* p) {
    uint32_t a;
    asm("{ .reg .u64 t; cvta.to.shared.u64 t, %1; cvt.u32.u64 %0, t; }"
        : "=r"(a) : "l"(p));
    return a;
}
// split 8 fp32 (two float4) -> uint4 of bf16 hi + uint4 of bf16 lo
__device__ __forceinline__ void split8(const float4 v0, const float4 v1,
                                       uint4& H, uint4& L) {
    float f[8] = {v0.x, v0.y, v0.z, v0.w, v1.x, v1.y, v1.z, v1.w};
    uint32_t h[4], l[4];
    #pragma unroll
    for (int i = 0; i < 4; i++) {
        __nv_bfloat16 ha = __float2bfloat16(f[2*i]);
        __nv_bfloat16 hb = __float2bfloat16(f[2*i+1]);
        __nv_bfloat16 la = __float2bfloat16(f[2*i]   - __bfloat162float(ha));
        __nv_bfloat16 lb = __float2bfloat16(f[2*i+1] - __bfloat162float(hb));
        h[i] = (uint32_t)__bfloat16_as_ushort(ha)
             | ((uint32_t)__bfloat16_as_ushort(hb) << 16);
        l[i] = (uint32_t)__bfloat16_as_ushort(la)
             | ((uint32_t)__bfloat16_as_ushort(lb) << 16);
    }
    H = make_uint4(h[0], h[1], h[2], h[3]);
    L = make_uint4(l[0], l[1], l[2], l[3]);
}

// ===========================================================================
// prep: split x (524288 u4) + 4 weights (4x131072 u4) into hi/lo arrays.
// One uint4 output pair (8 fp32 in) per thread. 1,048,576 threads.
// ===========================================================================
__global__ __launch_bounds__(256) void prep(
    const float* __restrict__ x,
    const float* __restrict__ wq, const float* __restrict__ wk,
    const float* __restrict__ wv, const float* __restrict__ wo)
{
    unsigned i = blockIdx.x * 256 + threadIdx.x;   // u4 index
    const float* src;
    uint4 *dh, *dl;
    unsigned off;
    if (i < 524288u) { src = x; dh = g_XH4; dl = g_XL4; off = i; }
    else {
        unsigned j = i - 524288u;
        unsigned w = j >> 17;                       // 0..3
        off = j & 131071u;
        src = (w == 0) ? wq : (w == 1) ? wk : (w == 2) ? wv : wo;
        dh = g_WH4 + (size_t)w * 131072u;
        dl = g_WL4 + (size_t)w * 131072u;
    }
    const float4* s4 = (const float4*)(src) + off * 2;
    uint4 H, L;
    split8(s4[0], s4[1], H, L);
    dh[off] = H;
    dl[off] = L;
}

// prep2: split fp32 concat g_Cc into g_CH4/g_CL4. 524288 threads.
__global__ __launch_bounds__(256) void prep2()
{
    unsigned i = blockIdx.x * 256 + threadIdx.x;
    const float4* s4 = (const float4*)(g_Cc) + i * 2;
    uint4 H, L;
    split8(s4[0], s4[1], H, L);
    g_CH4[i] = H;
    g_CL4[i] = L;
}

// ===========================================================================
// 3x-bf16-split GEMM on PRE-SPLIT inputs, ldmatrix fragment loads.
// C[m][c] = sum_k A[m][k] * W[c][k]   (NT, K=1024)
// BM=BN=128, BK=16, 256 threads (8 warps, 4x2 grid, warp tile 32x64).
// Tiles: bf16x2 words, row pitch 12 words. Double-buffered, 1 sync/chunk.
// Loader: 4 x LDG.128 + 4 x STS.128 per thread per chunk, zero math.
//   STS mapping: lane -> row (stride 12 words) -> all 32 banks, no conflict.
// mode 0: A={XH,XL}, W by blockIdx.z; head-split scatter to g_Q/K/V.
// mode 1: A={CH,CL}, W=wo(idx 3); row-major fp32 store to out.
// ===========================================================================
#define PITCH 12
#define TILEW (128*PITCH)                 // 1536 words per tile
#define TILEB (TILEW*4)                   // 6144 bytes
#define STAGEW (4*TILEW)
#define STAGEB (4*TILEB)                  // 24576 bytes
#define GEMM_SMEM (2*STAGEB)              // 49152 B

__global__ __launch_bounds__(256, 2) void gemm_bf16s(float* __restrict__ out,
                                                     int mode)
{
    extern __shared__ uint32_t smu[];
    const uint32_t smb = smem_u32(smu);

    const int tid = threadIdx.x;
    const int wid = tid >> 5;
    const int lane = tid & 31;
    const int G = lane >> 2;
    const int T = lane & 3;
    const int wm = wid & 3;
    const int wn = wid >> 2;
    const int rowBase = blockIdx.y * 128;
    const int colBase = blockIdx.x * 128;

    const int widx = (mode == 1) ? 3 : blockIdx.z;
    // source pointers per tile id {0:Ah, 1:Al, 2:Wh, 3:Wl}, in uint4 units.
    // row stride = 128 u4 (1024 bf16).
    const uint4* srcs[4];
    srcs[0] = ((mode == 1) ? g_CH4 : g_XH4) + (size_t)rowBase * 128;
    srcs[1] = ((mode == 1) ? g_CL4 : g_XL4) + (size_t)rowBase * 128;
    srcs[2] = g_WH4 + (size_t)widx * 131072u + (size_t)colBase * 128;
    srcs[3] = g_WL4 + (size_t)widx * 131072u + (size_t)colBase * 128;

    float acc[2][8][4];
    #pragma unroll
    for (int i = 0; i < 2; i++)
        #pragma unroll
        for (int j = 0; j < 8; j++)
            #pragma unroll
            for (int q = 0; q < 4; q++) acc[i][j][q] = 0.f;

    // ldmatrix per-lane byte offsets (within a tile)
    uint32_t aoff[2];
    #pragma unroll
    for (int mt = 0; mt < 2; mt++)
        aoff[mt] = (uint32_t)((wm * 32 + mt * 16 + (lane & 15)) * PITCH * 4
                              + ((lane >> 4) & 1) * 16);
    uint32_t boff[4];
    #pragma unroll
    for (int p = 0; p < 4; p++)
        boff[p] = (uint32_t)((wn * 64 + p * 16 + (lane & 7)
                              + ((lane >> 4) & 1) * 8) * PITCH * 4
                             + ((lane & 8) ? 16 : 0));

    // loader thread coords: per i-iteration covers one full tile (i = tile id)
    const int lr = tid & 127;               // row 0..127
    const int lh = tid >> 7;                // half 0..1 (8 bf16 each)
    // smem word offset within tile: lr*12 + lh*4
    const uint32_t s_off = (uint32_t)(lr * PITCH + lh * 4);

    uint4 pf[4];
    #pragma unroll
    for (int i = 0; i < 4; i++)
        pf[i] = srcs[i][(size_t)lr * 128 + 0 * 2 + lh];

    #pragma unroll 1
    for (int c = 0; c < 64; c++) {
        const uint32_t sbase = smb + (uint32_t)(c & 1) * STAGEB;
        uint32_t* stg = smu + (c & 1) * STAGEW;

        // store staged chunk c
        #pragma unroll
        for (int i = 0; i < 4; i++)
            *(uint4*)&stg[i * TILEW + s_off] = pf[i];
        __syncthreads();   // single barrier per chunk (double-buffer safe)

        // prefetch chunk c+1
        if (c < 63) {
            #pragma unroll
            for (int i = 0; i < 4; i++)
                pf[i] = srcs[i][(size_t)lr * 128 + (c + 1) * 2 + lh];
        }

        // fragment loads via ldmatrix
        uint32_t ah[2][4], al[2][4];
        ldm4(ah[0], sbase + aoff[0]);
        ldm4(ah[1], sbase + aoff[1]);
        ldm4(al[0], sbase + TILEB + aoff[0]);
        ldm4(al[1], sbase + TILEB + aoff[1]);

        #pragma unroll
        for (int p = 0; p < 4; p++) {
            uint32_t bh[4], bl[4];
            ldm4(bh, sbase + 2 * TILEB + boff[p]);
            ldm4(bl, sbase + 3 * TILEB + boff[p]);
            #pragma unroll
            for (int half = 0; half < 2; half++) {
                const int nt = 2 * p + half;
                const uint32_t bh0 = bh[2 * half], bh1 = bh[2 * half + 1];
                const uint32_t bl0 = bl[2 * half], bl1 = bl[2 * half + 1];
                #pragma unroll
                for (int mt = 0; mt < 2; mt++) {
                    mma_bf16(acc[mt][nt], ah[mt], bh0, bh1);  // hi*hi
                    mma_bf16(acc[mt][nt], ah[mt], bl0, bl1);  // hi*lo
                    mma_bf16(acc[mt][nt], al[mt], bh0, bh1);  // lo*hi
                }
            }
        }
    }

    if (mode == 0) {
        float* dst = (blockIdx.z == 0) ? g_Q : (blockIdx.z == 1 ? g_K : g_V);
        #pragma unroll
        for (int mt = 0; mt < 2; mt++) {
            #pragma unroll
            for (int fr = 0; fr < 2; fr++) {
                int m = rowBase + wm * 32 + mt * 16 + G + fr * 8;
                int b = m >> 11, n = m & 2047;
                size_t rb = ((size_t)(b << 4)) * SEQ;
                #pragma unroll
                for (int nt = 0; nt < 8; nt++) {
                    #pragma unroll
                    for (int fc = 0; fc < 2; fc++) {
                        int cc = colBase + wn * 64 + nt * 8 + 2 * T + fc;
                        int h = cc & 15, dd = cc >> 4;
                        dst[(((rb + (size_t)h * SEQ + n)) << 6) + dd] =
                            acc[mt][nt][fr * 2 + fc];
                    }
                }
            }
        }
    } else {
        #pragma unroll
        for (int mt = 0; mt < 2; mt++) {
            #pragma unroll
            for (int fr = 0; fr < 2; fr++) {
                int m = rowBase + wm * 32 + mt * 16 + G + fr * 8;
                float* op = out + (size_t)m * DMODEL + colBase + wn * 64;
                #pragma unroll
                for (int nt = 0; nt < 8; nt++)
                    *(float2*)&op[nt * 8 + 2 * T] =
                        make_float2(acc[mt][nt][fr * 2], acc[mt][nt][fr * 2 + 1]);
            }
        }
    }
}

// ===========================================================================
// Flash attention: fp16 S + fp16 PV (UNCHANGED from R10-passing version).
// ===========================================================================
#define ATTN_SMEM ((64*36 + 32*72) * 4)   // 18432 B

__global__ __launch_bounds__(128) void attn_tc()
{
    extern __shared__ uint32_t smu[];
    uint32_t* Ks = smu;                 // [64][36] half2 k-pairs
    uint32_t* Vp = smu + 64 * 36;       // [32][72] half2 k-pairs

    const int tid  = threadIdx.x;
    const int w    = tid >> 5;
    const int lane = tid & 31;
    const int G    = lane >> 2;
    const int T    = lane & 3;
    const int bh   = blockIdx.y;        // 0..31
    const int qB   = blockIdx.x * 64;

    const float* Qg = g_Q + (size_t)bh * SEQ * HDIM;
    const float* Kg = g_K + (size_t)bh * SEQ * HDIM;
    const float* Vg = g_V + (size_t)bh * SEQ * HDIM;

    uint32_t qa[4][4];
    {
        const float sc = 0.125f;
        const int rlo = qB + w * 16 + G;
        const float* q0 = Qg + (size_t)rlo * 64;
        const float* q1 = Qg + (size_t)(rlo + 8) * 64;
        #pragma unroll
        for (int kc = 0; kc < 4; kc++) {
            int k = kc * 16 + 2 * T;
            qa[kc][0] = ph2(q0[k] * sc,     q0[k + 1] * sc);
            qa[kc][1] = ph2(q1[k] * sc,     q1[k + 1] * sc);
            qa[kc][2] = ph2(q0[k + 8] * sc, q0[k + 9] * sc);
            qa[kc][3] = ph2(q1[k + 8] * sc, q1[k + 9] * sc);
        }
    }

    float o[8][4];
    #pragma unroll
    for (int nt = 0; nt < 8; nt++)
        #pragma unroll
        for (int q = 0; q < 4; q++) o[nt][q] = 0.f;
    float m_lo = -1e30f, m_hi = -1e30f, l_lo = 0.f, l_hi = 0.f;

    #pragma unroll 1
    for (int t = 0; t < SEQ / 64; t++) {
        __syncthreads();
        const float* Kt = Kg + (size_t)t * 64 * HDIM;
        const float* Vt = Vg + (size_t)t * 64 * HDIM;
        #pragma unroll
        for (int i = 0; i < 8; i++) {
            int f = tid + i * 128;
            int r = f >> 4;
            int c4 = (f & 15) << 2;
            float4 kv = *(const float4*)(Kt + r * 64 + c4);
            *(uint2*)&Ks[r * 36 + (c4 >> 1)] =
                make_uint2(ph2(kv.x, kv.y), ph2(kv.z, kv.w));
        }
        #pragma unroll
        for (int i = 0; i < 4; i++) {
            int f = tid + i * 128;
            int kp = f >> 4;
            int c4 = (f & 15) << 2;
            float4 v0 = *(const float4*)(Vt + (2 * kp) * 64 + c4);
            float4 v1 = *(const float4*)(Vt + (2 * kp + 1) * 64 + c4);
            *(uint4*)&Vp[kp * 72 + c4] =
                make_uint4(ph2(v0.x, v1.x), ph2(v0.y, v1.y),
                           ph2(v0.z, v1.z), ph2(v0.w, v1.w));
        }
        __syncthreads();

        float s[8][4];
        #pragma unroll
        for (int nt = 0; nt < 8; nt++)
            #pragma unroll
            for (int q = 0; q < 4; q++) s[nt][q] = 0.f;
        #pragma unroll
        for (int kc = 0; kc < 4; kc++) {
            #pragma unroll
            for (int nt = 0; nt < 8; nt++) {
                const uint32_t* kr = &Ks[(nt * 8 + G) * 36 + kc * 8 + T];
                mma_f16(s[nt], qa[kc], kr[0], kr[4]);
            }
        }

        float tmx_lo = -1e30f, tmx_hi = -1e30f;
        #pragma unroll
        for (int nt = 0; nt < 8; nt++) {
            tmx_lo = fmaxf(tmx_lo, fmaxf(s[nt][0], s[nt][1]));
            tmx_hi = fmaxf(tmx_hi, fmaxf(s[nt][2], s[nt][3]));
        }
        #pragma unroll
        for (int off = 1; off <= 2; off <<= 1) {
            tmx_lo = fmaxf(tmx_lo, __shfl_xor_sync(0xffffffffu, tmx_lo, off));
            tmx_hi = fmaxf(tmx_hi, __shfl_xor_sync(0xffffffffu, tmx_hi, off));
        }
        float nm_lo = fmaxf(m_lo, tmx_lo), nm_hi = fmaxf(m_hi, tmx_hi);
        float corr_lo = __expf(m_lo - nm_lo), corr_hi = __expf(m_hi - nm_hi);
        m_lo = nm_lo; m_hi = nm_hi;
        float sum_lo = 0.f, sum_hi = 0.f;
        #pragma unroll
        for (int nt = 0; nt < 8; nt++) {
            s[nt][0] = __expf(s[nt][0] - nm_lo);
            s[nt][1] = __expf(s[nt][1] - nm_lo);
            s[nt][2] = __expf(s[nt][2] - nm_hi);
            s[nt][3] = __expf(s[nt][3] - nm_hi);
            sum_lo += s[nt][0] + s[nt][1];
            sum_hi += s[nt][2] + s[nt][3];
            o[nt][0] *= corr_lo; o[nt][1] *= corr_lo;
            o[nt][2] *= corr_hi; o[nt][3] *= corr_hi;
        }
        #pragma unroll
        for (int off = 1; off <= 2; off <<= 1) {
            sum_lo += __shfl_xor_sync(0xffffffffu, sum_lo, off);
            sum_hi += __shfl_xor_sync(0xffffffffu, sum_hi, off);
        }
        l_lo = l_lo * corr_lo + sum_lo;
        l_hi = l_hi * corr_hi + sum_hi;

        #pragma unroll
        for (int kc = 0; kc < 4; kc++) {
            uint32_t pa[4];
            pa[0] = ph2(s[2 * kc][0],     s[2 * kc][1]);
            pa[1] = ph2(s[2 * kc][2],     s[2 * kc][3]);
            pa[2] = ph2(s[2 * kc + 1][0], s[2 * kc + 1][1]);
            pa[3] = ph2(s[2 * kc + 1][2], s[2 * kc + 1][3]);
            #pragma unroll
            for (int nt = 0; nt < 8; nt++) {
                int col = nt * 8 + G;
                uint32_t b0 = Vp[(8 * kc + T) * 72 + col];
                uint32_t b1 = Vp[(8 * kc + 4 + T) * 72 + col];
                mma_f16(o[nt], pa, b0, b1);
            }
        }
    }

    const int b = bh >> 4, h = bh & 15;
    const int row_lo = qB + w * 16 + G;
    const float il_lo = 1.0f / l_lo, il_hi = 1.0f / l_hi;
    size_t base_lo = ((size_t)(b * SEQ + row_lo)) * DMODEL + h * 64;
    size_t base_hi = base_lo + (size_t)8 * DMODEL;
    #pragma unroll
    for (int nt = 0; nt < 8; nt++) {
        *(float2*)&g_Cc[base_lo + nt * 8 + 2 * T] =
            make_float2(o[nt][0] * il_lo, o[nt][1] * il_lo);
        *(float2*)&g_Cc[base_hi + nt * 8 + 2 * T] =
            make_float2(o[nt][2] * il_hi, o[nt][3] * il_hi);
    }
}

extern "C" void kernel_launch(void* const* d_in, const int* in_sizes, int n_in,
                              void* d_out, int out_size)
{
    const float* x  = (const float*)d_in[0];
    const float* wq = (const float*)d_in[1];
    const float* wk = (const float*)d_in[2];
    const float* wv = (const float*)d_in[3];
    const float* wo = (const float*)d_in[4];
    float* out = (float*)d_out;

    cudaFuncSetAttribute(gemm_bf16s,
                         cudaFuncAttributeMaxDynamicSharedMemorySize, GEMM_SMEM);
    cudaFuncSetAttribute(attn_tc,
                         cudaFuncAttributeMaxDynamicSharedMemorySize, ATTN_SMEM);

    // 0) split x + weights into bf16 hi/lo (uint4-aligned arrays)
    prep<<<4096, 256>>>(x, wq, wk, wv, wo);

    // 1) QKV projections (pre-split, ldmatrix) with head-split scatter
    gemm_bf16s<<<dim3(DMODEL/128, MROWS/128, 3), 256, GEMM_SMEM>>>(nullptr, 0);

    // 2) Flash attention (fp16 S + fp16 PV) -> fp32 concat
    attn_tc<<<dim3(SEQ/64, BSZ*NHEAD), 128, ATTN_SMEM>>>();

    // 2b) split concat into bf16 hi/lo
    prep2<<<2048, 256>>>();

    // 3) Output projection (pre-split, ldmatrix) -> d_out
    gemm_bf16s<<<dim3(DMODEL/128, MROWS/128, 1), 256, GEMM_SMEM>>>(out, 1);
}

// round 14
// speedup vs baseline: 1.4269x; 1.4269x over previous
#include <cuda_runtime.h>
#include <cuda_fp16.h>
#include <cstdint>
#include <math.h>

#define BSZ 2
#define SEQ 2048
#define DMODEL 1024
#define NHEAD 16
#define HDIM 64
#define MROWS (BSZ*SEQ)   // 4096

// Scratch (allowed: __device__ globals, no runtime alloc)
__device__ float g_Q[BSZ*NHEAD*SEQ*HDIM];   // [b][h][n][dd]
__device__ float g_K[BSZ*NHEAD*SEQ*HDIM];
__device__ float g_V[BSZ*NHEAD*SEQ*HDIM];
__device__ float g_Cc[MROWS*DMODEL];        // concat [b*n][h*64+dd]

// ---------------------------------------------------------------------------
// mma.sync / ldmatrix helpers (portable PTX on plain compute_103 target)
// ---------------------------------------------------------------------------
// pack two fp32 -> f16x2 (first arg in LOW half)
__device__ __forceinline__ uint32_t ph2(float lo, float hi) {
    uint32_t r;
    asm("cvt.rn.f16x2.f32 %0, %1, %2;" : "=r"(r) : "f"(hi), "f"(lo));
    return r;
}
// f16: D += A(16x16) * B(16x8)
__device__ __forceinline__ void mma_f16(float* d, const uint32_t* a,
                                        uint32_t b0, uint32_t b1) {
    asm volatile(
        "mma.sync.aligned.m16n8k16.row.col.f32.f16.f16.f32 "
        "{%0,%1,%2,%3}, {%4,%5,%6,%7}, {%8,%9}, {%0,%1,%2,%3};"
        : "+f"(d[0]), "+f"(d[1]), "+f"(d[2]), "+f"(d[3])
        : "r"(a[0]), "r"(a[1]), "r"(a[2]), "r"(a[3]), "r"(b0), "r"(b1));
}
// ldmatrix x4: four 8x8 b16 matrices, per-lane row addresses
__device__ __forceinline__ void ldm4(uint32_t* r, uint32_t addr) {
    asm volatile(
        "ldmatrix.sync.aligned.m8n8.x4.shared.b16 {%0,%1,%2,%3}, [%4];"
        : "=r"(r[0]), "=r"(r[1]), "=r"(r[2]), "=r"(r[3]) : "r"(addr));
}
__device__ __forceinline__ uint32_t smem_u32(const void* p) {
    uint32_t a;
    asm("{ .reg .u64 t; cvta.to.shared.u64 t, %1; cvt.u32.u64 %0, t; }"
        : "=r"(a) : "l"(p));
    return a;
}
// (a,b) fp32 -> packed fp16x2 hi word + fp16x2 lo-residual word
__device__ __forceinline__ void split_pair_h(float a, float b,
                                             uint32_t& H, uint32_t& L) {
    __half ha = __float2half_rn(a);
    __half hb = __float2half_rn(b);
    __half la = __float2half_rn(a - __half2float(ha));
    __half lb = __float2half_rn(b - __half2float(hb));
    H = (uint32_t)__half_as_ushort(ha) | ((uint32_t)__half_as_ushort(hb) << 16);
    L = (uint32_t)__half_as_ushort(la) | ((uint32_t)__half_as_ushort(lb) << 16);
}

// ===========================================================================
// 2-pass fp16-split GEMM with ldmatrix fragment loads.
// C[m][c] = sum_k A[m][k] * W[c][k]   (NT, K=1024)
//   approx: A_h * (W_h + W_l)  — dropped A_l*W term is ~2^-12 relative.
// BM=BN=128, BK=16, 256 threads (8 warps, 4x2 grid, warp tile 32x64).
// Tiles: f16x2 words, row pitch 12 words; 3 tiles/stage {Ah, Wh, Wl}.
// Double-buffered, ONE __syncthreads per chunk. Per chunk per warp:
// 10 ldmatrix.x4 + 32 MMAs (was 12 + 48 with 3-pass bf16).
// mode 0: A=x, W by blockIdx.z in {wq,wk,wv}; head-split scatter to g_Q/K/V.
// mode 1: A=g_Cc, W=wo; row-major store to out.
// ===========================================================================
#define PITCH 12
#define TILEW (128*PITCH)                 // 1536 words per tile
#define TILEB (TILEW*4)                   // 6144 bytes
#define STAGEW (3*TILEW)
#define STAGEB (3*TILEB)                  // 18432 bytes
#define GEMM_SMEM (2*STAGEB)              // 36864 B

__global__ __launch_bounds__(256, 2) void gemm_f16s(
    const float* __restrict__ x,
    const float* __restrict__ wq, const float* __restrict__ wk,
    const float* __restrict__ wv, const float* __restrict__ wo,
    float* __restrict__ out, int mode)
{
    extern __shared__ uint32_t smu[];
    const uint32_t smb = smem_u32(smu);

    const int tid = threadIdx.x;
    const int wid = tid >> 5;
    const int lane = tid & 31;
    const int G = lane >> 2;
    const int T = lane & 3;
    const int wm = wid & 3;
    const int wn = wid >> 2;
    const int rowBase = blockIdx.y * 128;
    const int colBase = blockIdx.x * 128;

    const float* A = (mode == 1) ? (const float*)g_Cc : x;
    const float* W = (mode == 1) ? wo
                   : (blockIdx.z == 0 ? wq : (blockIdx.z == 1 ? wk : wv));
    const float* Aptr = A + (size_t)rowBase * DMODEL;
    const float* Wptr = W + (size_t)colBase * DMODEL;

    float acc[2][8][4];
    #pragma unroll
    for (int i = 0; i < 2; i++)
        #pragma unroll
        for (int j = 0; j < 8; j++)
            #pragma unroll
            for (int q = 0; q < 4; q++) acc[i][j][q] = 0.f;

    // ldmatrix per-lane byte offsets (within a tile)
    // A (m16k16, x4): row = wm*32 + mt*16 + (lane&15), byte half = (lane>>4)&1
    uint32_t aoff[2];
    #pragma unroll
    for (int mt = 0; mt < 2; mt++)
        aoff[mt] = (uint32_t)((wm * 32 + mt * 16 + (lane & 15)) * PITCH * 4
                              + ((lane >> 4) & 1) * 16);
    // B (two n8k16 frags per x4): rows cn0 + (lane&7) + ((lane>=16)?8:0),
    // byte half = (lane&8)?16:0.  p indexes nt pairs (nt=2p, 2p+1).
    uint32_t boff[4];
    #pragma unroll
    for (int p = 0; p < 4; p++)
        boff[p] = (uint32_t)((wn * 64 + p * 16 + (lane & 7)
                              + ((lane >> 4) & 1) * 8) * PITCH * 4
                             + ((lane & 8) ? 16 : 0));

    const int r0 = tid >> 2;                // 0..63
    const int q4 = (tid & 3) << 2;          // 0,4,8,12
    const int wd = (tid & 3) << 1;          // word col 0,2,4,6

    float4 av[2], wv4[2];
    av[0]  = *(const float4*)(Aptr + (size_t)r0 * DMODEL + q4);
    av[1]  = *(const float4*)(Aptr + (size_t)(r0 + 64) * DMODEL + q4);
    wv4[0] = *(const float4*)(Wptr + (size_t)r0 * DMODEL + q4);
    wv4[1] = *(const float4*)(Wptr + (size_t)(r0 + 64) * DMODEL + q4);

    #pragma unroll 1
    for (int c = 0; c < 64; c++) {
        const uint32_t sbase = smb + (uint32_t)(c & 1) * STAGEB;
        uint32_t* Ah = smu + (c & 1) * STAGEW;
        uint32_t* Wh = Ah + TILEW;
        uint32_t* Wl = Wh + TILEW;

        // store staged chunk c: A -> fp16 hi only; W -> fp16 hi + lo
        #pragma unroll
        for (int it = 0; it < 2; it++) {
            int rr = r0 + it * 64;
            *(uint2*)&Ah[rr * PITCH + wd] =
                make_uint2(ph2(av[it].x, av[it].y), ph2(av[it].z, av[it].w));
            uint32_t H0, L0, H1, L1;
            split_pair_h(wv4[it].x, wv4[it].y, H0, L0);
            split_pair_h(wv4[it].z, wv4[it].w, H1, L1);
            *(uint2*)&Wh[rr * PITCH + wd] = make_uint2(H0, H1);
            *(uint2*)&Wl[rr * PITCH + wd] = make_uint2(L0, L1);
        }
        __syncthreads();   // single barrier per chunk (double-buffer safe)

        // prefetch chunk c+1
        if (c < 63) {
            const int k0 = (c + 1) * 16;
            av[0]  = *(const float4*)(Aptr + (size_t)r0 * DMODEL + k0 + q4);
            av[1]  = *(const float4*)(Aptr + (size_t)(r0 + 64) * DMODEL + k0 + q4);
            wv4[0] = *(const float4*)(Wptr + (size_t)r0 * DMODEL + k0 + q4);
            wv4[1] = *(const float4*)(Wptr + (size_t)(r0 + 64) * DMODEL + k0 + q4);
        }

        // fragment loads via ldmatrix (A: 2x, B: 8x per chunk)
        uint32_t ah[2][4];
        ldm4(ah[0], sbase + aoff[0]);
        ldm4(ah[1], sbase + aoff[1]);

        #pragma unroll
        for (int p = 0; p < 4; p++) {
            uint32_t bh[4], bl[4];
            ldm4(bh, sbase + TILEB + boff[p]);
            ldm4(bl, sbase + 2 * TILEB + boff[p]);
            // nt = 2p uses bh[0],bh[1] / bl[0],bl[1]; nt = 2p+1 uses [2],[3]
            #pragma unroll
            for (int half = 0; half < 2; half++) {
                const int nt = 2 * p + half;
                const uint32_t bh0 = bh[2 * half], bh1 = bh[2 * half + 1];
                const uint32_t bl0 = bl[2 * half], bl1 = bl[2 * half + 1];
                #pragma unroll
                for (int mt = 0; mt < 2; mt++) {
                    mma_f16(acc[mt][nt], ah[mt], bh0, bh1);  // Ah * Wh
                    mma_f16(acc[mt][nt], ah[mt], bl0, bl1);  // Ah * Wl
                }
            }
        }
        // no trailing sync: store c+2 is ordered after compute c by
        // sync(c+1) + per-warp program order.
    }

    if (mode == 0) {
        float* dst = (blockIdx.z == 0) ? g_Q : (blockIdx.z == 1 ? g_K : g_V);
        #pragma unroll
        for (int mt = 0; mt < 2; mt++) {
            #pragma unroll
            for (int fr = 0; fr < 2; fr++) {
                int m = rowBase + wm * 32 + mt * 16 + G + fr * 8;
                int b = m >> 11, n = m & 2047;
                size_t rb = ((size_t)(b << 4)) * SEQ;
                #pragma unroll
                for (int nt = 0; nt < 8; nt++) {
                    #pragma unroll
                    for (int fc = 0; fc < 2; fc++) {
                        int cc = colBase + wn * 64 + nt * 8 + 2 * T + fc;
                        int h = cc & 15, dd = cc >> 4;
                        dst[(((rb + (size_t)h * SEQ + n)) << 6) + dd] =
                            acc[mt][nt][fr * 2 + fc];
                    }
                }
            }
        }
    } else {
        #pragma unroll
        for (int mt = 0; mt < 2; mt++) {
            #pragma unroll
            for (int fr = 0; fr < 2; fr++) {
                int m = rowBase + wm * 32 + mt * 16 + G + fr * 8;
                float* op = out + (size_t)m * DMODEL + colBase + wn * 64;
                #pragma unroll
                for (int nt = 0; nt < 8; nt++)
                    *(float2*)&op[nt * 8 + 2 * T] =
                        make_float2(acc[mt][nt][fr * 2], acc[mt][nt][fr * 2 + 1]);
            }
        }
    }
}

// ===========================================================================
// Flash attention: fp16 S + fp16 PV (UNCHANGED from R10-passing version).
// Grid (SEQ/64, B*H), 128 threads (4 warps). Warp: 16 q-rows, KV tiles of 64.
// ===========================================================================
#define ATTN_SMEM ((64*36 + 32*72) * 4)   // 18432 B

__global__ __launch_bounds__(128) void attn_tc()
{
    extern __shared__ uint32_t smu[];
    uint32_t* Ks = smu;                 // [64][36] half2 k-pairs
    uint32_t* Vp = smu + 64 * 36;       // [32][72] half2 k-pairs

    const int tid  = threadIdx.x;
    const int w    = tid >> 5;
    const int lane = tid & 31;
    const int G    = lane >> 2;
    const int T    = lane & 3;
    const int bh   = blockIdx.y;        // 0..31
    const int qB   = blockIdx.x * 64;

    const float* Qg = g_Q + (size_t)bh * SEQ * HDIM;
    const float* Kg = g_K + (size_t)bh * SEQ * HDIM;
    const float* Vg = g_V + (size_t)bh * SEQ * HDIM;

    uint32_t qa[4][4];
    {
        const float sc = 0.125f;
        const int rlo = qB + w * 16 + G;
        const float* q0 = Qg + (size_t)rlo * 64;
        const float* q1 = Qg + (size_t)(rlo + 8) * 64;
        #pragma unroll
        for (int kc = 0; kc < 4; kc++) {
            int k = kc * 16 + 2 * T;
            qa[kc][0] = ph2(q0[k] * sc,     q0[k + 1] * sc);
            qa[kc][1] = ph2(q1[k] * sc,     q1[k + 1] * sc);
            qa[kc][2] = ph2(q0[k + 8] * sc, q0[k + 9] * sc);
            qa[kc][3] = ph2(q1[k + 8] * sc, q1[k + 9] * sc);
        }
    }

    float o[8][4];
    #pragma unroll
    for (int nt = 0; nt < 8; nt++)
        #pragma unroll
        for (int q = 0; q < 4; q++) o[nt][q] = 0.f;
    float m_lo = -1e30f, m_hi = -1e30f, l_lo = 0.f, l_hi = 0.f;

    #pragma unroll 1
    for (int t = 0; t < SEQ / 64; t++) {
        __syncthreads();
        const float* Kt = Kg + (size_t)t * 64 * HDIM;
        const float* Vt = Vg + (size_t)t * 64 * HDIM;
        #pragma unroll
        for (int i = 0; i < 8; i++) {
            int f = tid + i * 128;
            int r = f >> 4;
            int c4 = (f & 15) << 2;
            float4 kv = *(const float4*)(Kt + r * 64 + c4);
            *(uint2*)&Ks[r * 36 + (c4 >> 1)] =
                make_uint2(ph2(kv.x, kv.y), ph2(kv.z, kv.w));
        }
        #pragma unroll
        for (int i = 0; i < 4; i++) {
            int f = tid + i * 128;
            int kp = f >> 4;
            int c4 = (f & 15) << 2;
            float4 v0 = *(const float4*)(Vt + (2 * kp) * 64 + c4);
            float4 v1 = *(const float4*)(Vt + (2 * kp + 1) * 64 + c4);
            *(uint4*)&Vp[kp * 72 + c4] =
                make_uint4(ph2(v0.x, v1.x), ph2(v0.y, v1.y),
                           ph2(v0.z, v1.z), ph2(v0.w, v1.w));
        }
        __syncthreads();

        float s[8][4];
        #pragma unroll
        for (int nt = 0; nt < 8; nt++)
            #pragma unroll
            for (int q = 0; q < 4; q++) s[nt][q] = 0.f;
        #pragma unroll
        for (int kc = 0; kc < 4; kc++) {
            #pragma unroll
            for (int nt = 0; nt < 8; nt++) {
                const uint32_t* kr = &Ks[(nt * 8 + G) * 36 + kc * 8 + T];
                mma_f16(s[nt], qa[kc], kr[0], kr[4]);
            }
        }

        float tmx_lo = -1e30f, tmx_hi = -1e30f;
        #pragma unroll
        for (int nt = 0; nt < 8; nt++) {
            tmx_lo = fmaxf(tmx_lo, fmaxf(s[nt][0], s[nt][1]));
            tmx_hi = fmaxf(tmx_hi, fmaxf(s[nt][2], s[nt][3]));
        }
        #pragma unroll
        for (int off = 1; off <= 2; off <<= 1) {
            tmx_lo = fmaxf(tmx_lo, __shfl_xor_sync(0xffffffffu, tmx_lo, off));
            tmx_hi = fmaxf(tmx_hi, __shfl_xor_sync(0xffffffffu, tmx_hi, off));
        }
        float nm_lo = fmaxf(m_lo, tmx_lo), nm_hi = fmaxf(m_hi, tmx_hi);
        float corr_lo = __expf(m_lo - nm_lo), corr_hi = __expf(m_hi - nm_hi);
        m_lo = nm_lo; m_hi = nm_hi;
        float sum_lo = 0.f, sum_hi = 0.f;
        #pragma unroll
        for (int nt = 0; nt < 8; nt++) {
            s[nt][0] = __expf(s[nt][0] - nm_lo);
            s[nt][1] = __expf(s[nt][1] - nm_lo);
            s[nt][2] = __expf(s[nt][2] - nm_hi);
            s[nt][3] = __expf(s[nt][3] - nm_hi);
            sum_lo += s[nt][0] + s[nt][1];
            sum_hi += s[nt][2] + s[nt][3];
            o[nt][0] *= corr_lo; o[nt][1] *= corr_lo;
            o[nt][2] *= corr_hi; o[nt][3] *= corr_hi;
        }
        #pragma unroll
        for (int off = 1; off <= 2; off <<= 1) {
            sum_lo += __shfl_xor_sync(0xffffffffu, sum_lo, off);
            sum_hi += __shfl_xor_sync(0xffffffffu, sum_hi, off);
        }
        l_lo = l_lo * corr_lo + sum_lo;
        l_hi = l_hi * corr_hi + sum_hi;

        #pragma unroll
        for (int kc = 0; kc < 4; kc++) {
            uint32_t pa[4];
            pa[0] = ph2(s[2 * kc][0],     s[2 * kc][1]);
            pa[1] = ph2(s[2 * kc][2],     s[2 * kc][3]);
            pa[2] = ph2(s[2 * kc + 1][0], s[2 * kc + 1][1]);
            pa[3] = ph2(s[2 * kc + 1][2], s[2 * kc + 1][3]);
            #pragma unroll
            for (int nt = 0; nt < 8; nt++) {
                int col = nt * 8 + G;
                uint32_t b0 = Vp[(8 * kc + T) * 72 + col];
                uint32_t b1 = Vp[(8 * kc + 4 + T) * 72 + col];
                mma_f16(o[nt], pa, b0, b1);
            }
        }
    }

    const int b = bh >> 4, h = bh & 15;
    const int row_lo = qB + w * 16 + G;
    const float il_lo = 1.0f / l_lo, il_hi = 1.0f / l_hi;
    size_t base_lo = ((size_t)(b * SEQ + row_lo)) * DMODEL + h * 64;
    size_t base_hi = base_lo + (size_t)8 * DMODEL;
    #pragma unroll
    for (int nt = 0; nt < 8; nt++) {
        *(float2*)&g_Cc[base_lo + nt * 8 + 2 * T] =
            make_float2(o[nt][0] * il_lo, o[nt][1] * il_lo);
        *(float2*)&g_Cc[base_hi + nt * 8 + 2 * T] =
            make_float2(o[nt][2] * il_hi, o[nt][3] * il_hi);
    }
}

extern "C" void kernel_launch(void* const* d_in, const int* in_sizes, int n_in,
                              void* d_out, int out_size)
{
    const float* x  = (const float*)d_in[0];
    const float* wq = (const float*)d_in[1];
    const float* wk = (const float*)d_in[2];
    const float* wv = (const float*)d_in[3];
    const float* wo = (const float*)d_in[4];
    float* out = (float*)d_out;

    cudaFuncSetAttribute(gemm_f16s,
                         cudaFuncAttributeMaxDynamicSharedMemorySize, GEMM_SMEM);
    cudaFuncSetAttribute(attn_tc,
                         cudaFuncAttributeMaxDynamicSharedMemorySize, ATTN_SMEM);

    // 1) QKV projections (2-pass fp16-split, ldmatrix) + head-split scatter
    gemm_f16s<<<dim3(DMODEL/128, MROWS/128, 3), 256, GEMM_SMEM>>>(
        x, wq, wk, wv, wo, nullptr, 0);

    // 2) Flash attention (fp16 S + fp16 PV) -> concat
    attn_tc<<<dim3(SEQ/64, BSZ*NHEAD), 128, ATTN_SMEM>>>();

    // 3) Output projection (2-pass fp16-split, ldmatrix) -> d_out
    gemm_f16s<<<dim3(DMODEL/128, MROWS/128, 1), 256, GEMM_SMEM>>>(
        x, wq, wk, wv, wo, out, 1);
}

// round 15
// speedup vs baseline: 1.6972x; 1.1895x over previous
#include <cuda_runtime.h>
#include <cuda_fp16.h>
#include <cstdint>
#include <math.h>

#define BSZ 2
#define SEQ 2048
#define DMODEL 1024
#define NHEAD 16
#define HDIM 64
#define MROWS (BSZ*SEQ)   // 4096

// Scratch (allowed: __device__ globals, no runtime alloc)
__device__ float g_Q[BSZ*NHEAD*SEQ*HDIM];   // [b][h][n][dd]
__device__ float g_K[BSZ*NHEAD*SEQ*HDIM];
__device__ float g_V[BSZ*NHEAD*SEQ*HDIM];
__device__ float g_Cc[MROWS*DMODEL];        // concat [b*n][h*64+dd]

// ---------------------------------------------------------------------------
// mma.sync / ldmatrix helpers (portable PTX on plain compute_103 target)
// ---------------------------------------------------------------------------
// pack two fp32 -> f16x2 (first arg in LOW half)
__device__ __forceinline__ uint32_t ph2(float lo, float hi) {
    uint32_t r;
    asm("cvt.rn.f16x2.f32 %0, %1, %2;" : "=r"(r) : "f"(hi), "f"(lo));
    return r;
}
// f16: D += A(16x16) * B(16x8)
__device__ __forceinline__ void mma_f16(float* d, const uint32_t* a,
                                        uint32_t b0, uint32_t b1) {
    asm volatile(
        "mma.sync.aligned.m16n8k16.row.col.f32.f16.f16.f32 "
        "{%0,%1,%2,%3}, {%4,%5,%6,%7}, {%8,%9}, {%0,%1,%2,%3};"
        : "+f"(d[0]), "+f"(d[1]), "+f"(d[2]), "+f"(d[3])
        : "r"(a[0]), "r"(a[1]), "r"(a[2]), "r"(a[3]), "r"(b0), "r"(b1));
}
// ldmatrix x4: four 8x8 b16 matrices, per-lane row addresses
__device__ __forceinline__ void ldm4(uint32_t* r, uint32_t addr) {
    asm volatile(
        "ldmatrix.sync.aligned.m8n8.x4.shared.b16 {%0,%1,%2,%3}, [%4];"
        : "=r"(r[0]), "=r"(r[1]), "=r"(r[2]), "=r"(r[3]) : "r"(addr));
}
__device__ __forceinline__ uint32_t smem_u32(const void* p) {
    uint32_t a;
    asm("{ .reg .u64 t; cvta.to.shared.u64 t, %1; cvt.u32.u64 %0, t; }"
        : "=r"(a) : "l"(p));
    return a;
}

// ===========================================================================
// Single-pass fp16 GEMM with ldmatrix fragment loads.
// C[m][c] = sum_k A[m][k] * W[c][k]   (NT, K=1024), both inputs fp16-rounded
// (input-rounding error ~2^-12 random-walk => ~3.5e-4 relative per GEMM).
// BM=BN=128, BK=16, 256 threads (8 warps, 4x2 grid, warp tile 32x64).
// Tiles: f16x2 words, row pitch 12 words; 2 tiles/stage {Ah, Wh}.
// Double-buffered, ONE __syncthreads per chunk. Per chunk per warp:
// 6 ldmatrix.x4 + 16 MMAs (was 10 + 32 with 2-pass).
// mode 0: A=x, W by blockIdx.z in {wq,wk,wv}; head-split scatter to g_Q/K/V.
// mode 1: A=g_Cc, W=wo; row-major store to out.
// ===========================================================================
#define PITCH 12
#define TILEW (128*PITCH)                 // 1536 words per tile
#define TILEB (TILEW*4)                   // 6144 bytes
#define STAGEW (2*TILEW)
#define STAGEB (2*TILEB)                  // 12288 bytes
#define GEMM_SMEM (2*STAGEB)              // 24576 B

__global__ __launch_bounds__(256, 2) void gemm_f16s(
    const float* __restrict__ x,
    const float* __restrict__ wq, const float* __restrict__ wk,
    const float* __restrict__ wv, const float* __restrict__ wo,
    float* __restrict__ out, int mode)
{
    extern __shared__ uint32_t smu[];
    const uint32_t smb = smem_u32(smu);

    const int tid = threadIdx.x;
    const int wid = tid >> 5;
    const int lane = tid & 31;
    const int G = lane >> 2;
    const int T = lane & 3;
    const int wm = wid & 3;
    const int wn = wid >> 2;
    const int rowBase = blockIdx.y * 128;
    const int colBase = blockIdx.x * 128;

    const float* A = (mode == 1) ? (const float*)g_Cc : x;
    const float* W = (mode == 1) ? wo
                   : (blockIdx.z == 0 ? wq : (blockIdx.z == 1 ? wk : wv));
    const float* Aptr = A + (size_t)rowBase * DMODEL;
    const float* Wptr = W + (size_t)colBase * DMODEL;

    float acc[2][8][4];
    #pragma unroll
    for (int i = 0; i < 2; i++)
        #pragma unroll
        for (int j = 0; j < 8; j++)
            #pragma unroll
            for (int q = 0; q < 4; q++) acc[i][j][q] = 0.f;

    // ldmatrix per-lane byte offsets (within a tile)
    // A (m16k16, x4): row = wm*32 + mt*16 + (lane&15), byte half = (lane>>4)&1
    uint32_t aoff[2];
    #pragma unroll
    for (int mt = 0; mt < 2; mt++)
        aoff[mt] = (uint32_t)((wm * 32 + mt * 16 + (lane & 15)) * PITCH * 4
                              + ((lane >> 4) & 1) * 16);
    // B (two n8k16 frags per x4): rows cn0 + (lane&7) + ((lane>=16)?8:0),
    // byte half = (lane&8)?16:0.  p indexes nt pairs (nt=2p, 2p+1).
    uint32_t boff[4];
    #pragma unroll
    for (int p = 0; p < 4; p++)
        boff[p] = (uint32_t)((wn * 64 + p * 16 + (lane & 7)
                              + ((lane >> 4) & 1) * 8) * PITCH * 4
                             + ((lane & 8) ? 16 : 0));

    const int r0 = tid >> 2;                // 0..63
    const int q4 = (tid & 3) << 2;          // 0,4,8,12
    const int wd = (tid & 3) << 1;          // word col 0,2,4,6

    float4 av[2], wv4[2];
    av[0]  = *(const float4*)(Aptr + (size_t)r0 * DMODEL + q4);
    av[1]  = *(const float4*)(Aptr + (size_t)(r0 + 64) * DMODEL + q4);
    wv4[0] = *(const float4*)(Wptr + (size_t)r0 * DMODEL + q4);
    wv4[1] = *(const float4*)(Wptr + (size_t)(r0 + 64) * DMODEL + q4);

    #pragma unroll 1
    for (int c = 0; c < 64; c++) {
        const uint32_t sbase = smb + (uint32_t)(c & 1) * STAGEB;
        uint32_t* Ah = smu + (c & 1) * STAGEW;
        uint32_t* Wh = Ah + TILEW;

        // store staged chunk c: straight fp16 packs, zero split math
        #pragma unroll
        for (int it = 0; it < 2; it++) {
            int rr = r0 + it * 64;
            *(uint2*)&Ah[rr * PITCH + wd] =
                make_uint2(ph2(av[it].x, av[it].y), ph2(av[it].z, av[it].w));
            *(uint2*)&Wh[rr * PITCH + wd] =
                make_uint2(ph2(wv4[it].x, wv4[it].y), ph2(wv4[it].z, wv4[it].w));
        }
        __syncthreads();   // single barrier per chunk (double-buffer safe)

        // prefetch chunk c+1
        if (c < 63) {
            const int k0 = (c + 1) * 16;
            av[0]  = *(const float4*)(Aptr + (size_t)r0 * DMODEL + k0 + q4);
            av[1]  = *(const float4*)(Aptr + (size_t)(r0 + 64) * DMODEL + k0 + q4);
            wv4[0] = *(const float4*)(Wptr + (size_t)r0 * DMODEL + k0 + q4);
            wv4[1] = *(const float4*)(Wptr + (size_t)(r0 + 64) * DMODEL + k0 + q4);
        }

        // fragment loads via ldmatrix (A: 2x, B: 4x per chunk)
        uint32_t ah[2][4];
        ldm4(ah[0], sbase + aoff[0]);
        ldm4(ah[1], sbase + aoff[1]);

        #pragma unroll
        for (int p = 0; p < 4; p++) {
            uint32_t bh[4];
            ldm4(bh, sbase + TILEB + boff[p]);
            // nt = 2p uses bh[0],bh[1]; nt = 2p+1 uses bh[2],bh[3]
            #pragma unroll
            for (int half = 0; half < 2; half++) {
                const int nt = 2 * p + half;
                const uint32_t b0 = bh[2 * half], b1 = bh[2 * half + 1];
                #pragma unroll
                for (int mt = 0; mt < 2; mt++)
                    mma_f16(acc[mt][nt], ah[mt], b0, b1);
            }
        }
        // no trailing sync: store c+2 is ordered after compute c by
        // sync(c+1) + per-warp program order.
    }

    if (mode == 0) {
        float* dst = (blockIdx.z == 0) ? g_Q : (blockIdx.z == 1 ? g_K : g_V);
        #pragma unroll
        for (int mt = 0; mt < 2; mt++) {
            #pragma unroll
            for (int fr = 0; fr < 2; fr++) {
                int m = rowBase + wm * 32 + mt * 16 + G + fr * 8;
                int b = m >> 11, n = m & 2047;
                size_t rb = ((size_t)(b << 4)) * SEQ;
                #pragma unroll
                for (int nt = 0; nt < 8; nt++) {
                    #pragma unroll
                    for (int fc = 0; fc < 2; fc++) {
                        int cc = colBase + wn * 64 + nt * 8 + 2 * T + fc;
                        int h = cc & 15, dd = cc >> 4;
                        dst[(((rb + (size_t)h * SEQ + n)) << 6) + dd] =
                            acc[mt][nt][fr * 2 + fc];
                    }
                }
            }
        }
    } else {
        #pragma unroll
        for (int mt = 0; mt < 2; mt++) {
            #pragma unroll
            for (int fr = 0; fr < 2; fr++) {
                int m = rowBase + wm * 32 + mt * 16 + G + fr * 8;
                float* op = out + (size_t)m * DMODEL + colBase + wn * 64;
                #pragma unroll
                for (int nt = 0; nt < 8; nt++)
                    *(float2*)&op[nt * 8 + 2 * T] =
                        make_float2(acc[mt][nt][fr * 2], acc[mt][nt][fr * 2 + 1]);
            }
        }
    }
}

// ===========================================================================
// Flash attention: fp16 S + fp16 PV (UNCHANGED from R10-passing version).
// Grid (SEQ/64, B*H), 128 threads (4 warps). Warp: 16 q-rows, KV tiles of 64.
// ===========================================================================
#define ATTN_SMEM ((64*36 + 32*72) * 4)   // 18432 B

__global__ __launch_bounds__(128) void attn_tc()
{
    extern __shared__ uint32_t smu[];
    uint32_t* Ks = smu;                 // [64][36] half2 k-pairs
    uint32_t* Vp = smu + 64 * 36;       // [32][72] half2 k-pairs

    const int tid  = threadIdx.x;
    const int w    = tid >> 5;
    const int lane = tid & 31;
    const int G    = lane >> 2;
    const int T    = lane & 3;
    const int bh   = blockIdx.y;        // 0..31
    const int qB   = blockIdx.x * 64;

    const float* Qg = g_Q + (size_t)bh * SEQ * HDIM;
    const float* Kg = g_K + (size_t)bh * SEQ * HDIM;
    const float* Vg = g_V + (size_t)bh * SEQ * HDIM;

    uint32_t qa[4][4];
    {
        const float sc = 0.125f;
        const int rlo = qB + w * 16 + G;
        const float* q0 = Qg + (size_t)rlo * 64;
        const float* q1 = Qg + (size_t)(rlo + 8) * 64;
        #pragma unroll
        for (int kc = 0; kc < 4; kc++) {
            int k = kc * 16 + 2 * T;
            qa[kc][0] = ph2(q0[k] * sc,     q0[k + 1] * sc);
            qa[kc][1] = ph2(q1[k] * sc,     q1[k + 1] * sc);
            qa[kc][2] = ph2(q0[k + 8] * sc, q0[k + 9] * sc);
            qa[kc][3] = ph2(q1[k + 8] * sc, q1[k + 9] * sc);
        }
    }

    float o[8][4];
    #pragma unroll
    for (int nt = 0; nt < 8; nt++)
        #pragma unroll
        for (int q = 0; q < 4; q++) o[nt][q] = 0.f;
    float m_lo = -1e30f, m_hi = -1e30f, l_lo = 0.f, l_hi = 0.f;

    #pragma unroll 1
    for (int t = 0; t < SEQ / 64; t++) {
        __syncthreads();
        const float* Kt = Kg + (size_t)t * 64 * HDIM;
        const float* Vt = Vg + (size_t)t * 64 * HDIM;
        #pragma unroll
        for (int i = 0; i < 8; i++) {
            int f = tid + i * 128;
            int r = f >> 4;
            int c4 = (f & 15) << 2;
            float4 kv = *(const float4*)(Kt + r * 64 + c4);
            *(uint2*)&Ks[r * 36 + (c4 >> 1)] =
                make_uint2(ph2(kv.x, kv.y), ph2(kv.z, kv.w));
        }
        #pragma unroll
        for (int i = 0; i < 4; i++) {
            int f = tid + i * 128;
            int kp = f >> 4;
            int c4 = (f & 15) << 2;
            float4 v0 = *(const float4*)(Vt + (2 * kp) * 64 + c4);
            float4 v1 = *(const float4*)(Vt + (2 * kp + 1) * 64 + c4);
            *(uint4*)&Vp[kp * 72 + c4] =
                make_uint4(ph2(v0.x, v1.x), ph2(v0.y, v1.y),
                           ph2(v0.z, v1.z), ph2(v0.w, v1.w));
        }
        __syncthreads();

        float s[8][4];
        #pragma unroll
        for (int nt = 0; nt < 8; nt++)
            #pragma unroll
            for (int q = 0; q < 4; q++) s[nt][q] = 0.f;
        #pragma unroll
        for (int kc = 0; kc < 4; kc++) {
            #pragma unroll
            for (int nt = 0; nt < 8; nt++) {
                const uint32_t* kr = &Ks[(nt * 8 + G) * 36 + kc * 8 + T];
                mma_f16(s[nt], qa[kc], kr[0], kr[4]);
            }
        }

        float tmx_lo = -1e30f, tmx_hi = -1e30f;
        #pragma unroll
        for (int nt = 0; nt < 8; nt++) {
            tmx_lo = fmaxf(tmx_lo, fmaxf(s[nt][0], s[nt][1]));
            tmx_hi = fmaxf(tmx_hi, fmaxf(s[nt][2], s[nt][3]));
        }
        #pragma unroll
        for (int off = 1; off <= 2; off <<= 1) {
            tmx_lo = fmaxf(tmx_lo, __shfl_xor_sync(0xffffffffu, tmx_lo, off));
            tmx_hi = fmaxf(tmx_hi, __shfl_xor_sync(0xffffffffu, tmx_hi, off));
        }
        float nm_lo = fmaxf(m_lo, tmx_lo), nm_hi = fmaxf(m_hi, tmx_hi);
        float corr_lo = __expf(m_lo - nm_lo), corr_hi = __expf(m_hi - nm_hi);
        m_lo = nm_lo; m_hi = nm_hi;
        float sum_lo = 0.f, sum_hi = 0.f;
        #pragma unroll
        for (int nt = 0; nt < 8; nt++) {
            s[nt][0] = __expf(s[nt][0] - nm_lo);
            s[nt][1] = __expf(s[nt][1] - nm_lo);
            s[nt][2] = __expf(s[nt][2] - nm_hi);
            s[nt][3] = __expf(s[nt][3] - nm_hi);
            sum_lo += s[nt][0] + s[nt][1];
            sum_hi += s[nt][2] + s[nt][3];
            o[nt][0] *= corr_lo; o[nt][1] *= corr_lo;
            o[nt][2] *= corr_hi; o[nt][3] *= corr_hi;
        }
        #pragma unroll
        for (int off = 1; off <= 2; off <<= 1) {
            sum_lo += __shfl_xor_sync(0xffffffffu, sum_lo, off);
            sum_hi += __shfl_xor_sync(0xffffffffu, sum_hi, off);
        }
        l_lo = l_lo * corr_lo + sum_lo;
        l_hi = l_hi * corr_hi + sum_hi;

        #pragma unroll
        for (int kc = 0; kc < 4; kc++) {
            uint32_t pa[4];
            pa[0] = ph2(s[2 * kc][0],     s[2 * kc][1]);
            pa[1] = ph2(s[2 * kc][2],     s[2 * kc][3]);
            pa[2] = ph2(s[2 * kc + 1][0], s[2 * kc + 1][1]);
            pa[3] = ph2(s[2 * kc + 1][2], s[2 * kc + 1][3]);
            #pragma unroll
            for (int nt = 0; nt < 8; nt++) {
                int col = nt * 8 + G;
                uint32_t b0 = Vp[(8 * kc + T) * 72 + col];
                uint32_t b1 = Vp[(8 * kc + 4 + T) * 72 + col];
                mma_f16(o[nt], pa, b0, b1);
            }
        }
    }

    const int b = bh >> 4, h = bh & 15;
    const int row_lo = qB + w * 16 + G;
    const float il_lo = 1.0f / l_lo, il_hi = 1.0f / l_hi;
    size_t base_lo = ((size_t)(b * SEQ + row_lo)) * DMODEL + h * 64;
    size_t base_hi = base_lo + (size_t)8 * DMODEL;
    #pragma unroll
    for (int nt = 0; nt < 8; nt++) {
        *(float2*)&g_Cc[base_lo + nt * 8 + 2 * T] =
            make_float2(o[nt][0] * il_lo, o[nt][1] * il_lo);
        *(float2*)&g_Cc[base_hi + nt * 8 + 2 * T] =
            make_float2(o[nt][2] * il_hi, o[nt][3] * il_hi);
    }
}

extern "C" void kernel_launch(void* const* d_in, const int* in_sizes, int n_in,
                              void* d_out, int out_size)
{
    const float* x  = (const float*)d_in[0];
    const float* wq = (const float*)d_in[1];
    const float* wk = (const float*)d_in[2];
    const float* wv = (const float*)d_in[3];
    const float* wo = (const float*)d_in[4];
    float* out = (float*)d_out;

    cudaFuncSetAttribute(gemm_f16s,
                         cudaFuncAttributeMaxDynamicSharedMemorySize, GEMM_SMEM);
    cudaFuncSetAttribute(attn_tc,
                         cudaFuncAttributeMaxDynamicSharedMemorySize, ATTN_SMEM);

    // 1) QKV projections (single-pass fp16, ldmatrix) + head-split scatter
    gemm_f16s<<<dim3(DMODEL/128, MROWS/128, 3), 256, GEMM_SMEM>>>(
        x, wq, wk, wv, wo, nullptr, 0);

    // 2) Flash attention (fp16 S + fp16 PV) -> concat
    attn_tc<<<dim3(SEQ/64, BSZ*NHEAD), 128, ATTN_SMEM>>>();

    // 3) Output projection (single-pass fp16, ldmatrix) -> d_out
    gemm_f16s<<<dim3(DMODEL/128, MROWS/128, 1), 256, GEMM_SMEM>>>(
        x, wq, wk, wv, wo, out, 1);
}

// round 17
// speedup vs baseline: 1.8388x; 1.0834x over previous
#include <cuda_runtime.h>
#include <cuda_fp16.h>
#include <cstdint>
#include <math.h>

#define BSZ 2
#define SEQ 2048
#define DMODEL 1024
#define NHEAD 16
#define HDIM 64
#define MROWS (BSZ*SEQ)   // 4096

// Scratch (allowed: __device__ globals, no runtime alloc)
__device__ float g_Q[BSZ*NHEAD*SEQ*HDIM];   // [b][h][n][dd]
__device__ float g_K[BSZ*NHEAD*SEQ*HDIM];
__device__ float g_V[BSZ*NHEAD*SEQ*HDIM];
// fp16 operands as uint4 arrays (16B-aligned by type); 1 uint4 = 8 halfs
__device__ uint4 g_Xh4[MROWS*DMODEL/8];        // fp16(x)
__device__ uint4 g_Wh4[4*DMODEL*DMODEL/8];     // fp16(wq,wk,wv,wo)
__device__ uint4 g_Ch4[MROWS*DMODEL/8];        // fp16 concat (attn output)

// ---------------------------------------------------------------------------
// mma.sync / ldmatrix / cp.async helpers (portable PTX, plain compute_103)
// ---------------------------------------------------------------------------
// pack two fp32 -> f16x2 (first arg in LOW half)
__device__ __forceinline__ uint32_t ph2(float lo, float hi) {
    uint32_t r;
    asm("cvt.rn.f16x2.f32 %0, %1, %2;" : "=r"(r) : "f"(hi), "f"(lo));
    return r;
}
// f16: D += A(16x16) * B(16x8)
__device__ __forceinline__ void mma_f16(float* d, const uint32_t* a,
                                        uint32_t b0, uint32_t b1) {
    asm volatile(
        "mma.sync.aligned.m16n8k16.row.col.f32.f16.f16.f32 "
        "{%0,%1,%2,%3}, {%4,%5,%6,%7}, {%8,%9}, {%0,%1,%2,%3};"
        : "+f"(d[0]), "+f"(d[1]), "+f"(d[2]), "+f"(d[3])
        : "r"(a[0]), "r"(a[1]), "r"(a[2]), "r"(a[3]), "r"(b0), "r"(b1));
}
__device__ __forceinline__ void ldm4(uint32_t* r, uint32_t addr) {
    asm volatile(
        "ldmatrix.sync.aligned.m8n8.x4.shared.b16 {%0,%1,%2,%3}, [%4];"
        : "=r"(r[0]), "=r"(r[1]), "=r"(r[2]), "=r"(r[3]) : "r"(addr));
}
__device__ __forceinline__ uint32_t smem_u32(const void* p) {
    uint32_t a;
    asm("{ .reg .u64 t; cvta.to.shared.u64 t, %1; cvt.u32.u64 %0, t; }"
        : "=r"(a) : "l"(p));
    return a;
}
__device__ __forceinline__ void cp16(uint32_t dst, const void* src) {
    asm volatile("cp.async.cg.shared.global [%0], [%1], 16;"
                 :: "r"(dst), "l"(src));
}

// ===========================================================================
// prep: fp16-convert x (524288 u4) + 4 weights (524288 u4). 8 fp32 / thread.
// ===========================================================================
__global__ __launch_bounds__(256) void prep(
    const float* __restrict__ x,
    const float* __restrict__ wq, const float* __restrict__ wk,
    const float* __restrict__ wv, const float* __restrict__ wo)
{
    unsigned i = blockIdx.x * 256 + threadIdx.x;   // output u4 index
    const float* src;
    uint4* dst;
    unsigned off;
    if (i < 524288u) { src = x; dst = g_Xh4; off = i; }
    else {
        unsigned j = i - 524288u;
        unsigned w = j >> 17;                       // 0..3
        off = j & 131071u;
        src = (w == 0) ? wq : (w == 1) ? wk : (w == 2) ? wv : wo;
        dst = g_Wh4 + (size_t)w * 131072u;
    }
    const float4* s4 = (const float4*)src + (size_t)off * 2;
    float4 a = s4[0], b = s4[1];
    dst[off] = make_uint4(ph2(a.x, a.y), ph2(a.z, a.w),
                          ph2(b.x, b.y), ph2(b.z, b.w));
}

// ===========================================================================
// Single-pass fp16 GEMM, cp.async 4-stage pipeline + ldmatrix.
// C[m][c] = sum_k A[m][k] * W[c][k]   (NT, K=1024), fp16 inputs (pre-conv).
// BM=BN=128, BK=16, 256 threads (8 warps, 4x2 grid, warp tile 32x64).
// Tiles: f16x2 words, row pitch 12 words (48B); 2 tiles/stage {Ah, Wh}.
// Loader: 2 x cp.async.cg 16B per thread per chunk (zero math, fp16 bytes).
// Ring of 4 stages; wait_group 2 => 3 chunks of latency cover.
// mode 0: A=g_Xh4, W by blockIdx.z; head-split scatter to g_Q/K/V (fp32).
// mode 1: A=g_Ch4, W=wo(idx 3); row-major fp32 store to out.
// ===========================================================================
#define PITCH 12
#define TILEW (128*PITCH)                 // 1536 words per tile
#define TILEB (TILEW*4)                   // 6144 bytes
#define STAGEB (2*TILEB)                  // 12288 bytes
#define NSTAGE 4
#define GEMM_SMEM (NSTAGE*STAGEB)         // 49152 B

__global__ __launch_bounds__(256, 2) void gemm_f16a(float* __restrict__ out,
                                                    int mode)
{
    extern __shared__ uint32_t smu[];
    const uint32_t smb = smem_u32(smu);

    const int tid = threadIdx.x;
    const int wid = tid >> 5;
    const int lane = tid & 31;
    const int G = lane >> 2;
    const int T = lane & 3;
    const int wm = wid & 3;
    const int wn = wid >> 2;
    const int rowBase = blockIdx.y * 128;
    const int colBase = blockIdx.x * 128;

    const int widx = (mode == 1) ? 3 : blockIdx.z;
    // u4 row stride = 128 (1024 halfs per row)
    const uint4* Asrc = ((mode == 1) ? g_Ch4 : g_Xh4) + (size_t)rowBase * 128;
    const uint4* Wsrc = g_Wh4 + (size_t)widx * 131072u + (size_t)colBase * 128;

    float acc[2][8][4];
    #pragma unroll
    for (int i = 0; i < 2; i++)
        #pragma unroll
        for (int j = 0; j < 8; j++)
            #pragma unroll
            for (int q = 0; q < 4; q++) acc[i][j][q] = 0.f;

    // ldmatrix per-lane byte offsets (within a tile) — identical to R15
    uint32_t aoff[2];
    #pragma unroll
    for (int mt = 0; mt < 2; mt++)
        aoff[mt] = (uint32_t)((wm * 32 + mt * 16 + (lane & 15)) * PITCH * 4
                              + ((lane >> 4) & 1) * 16);
    uint32_t boff[4];
    #pragma unroll
    for (int p = 0; p < 4; p++)
        boff[p] = (uint32_t)((wn * 64 + p * 16 + (lane & 7)
                              + ((lane >> 4) & 1) * 8) * PITCH * 4
                             + ((lane & 8) ? 16 : 0));

    // cp.async loader coords: 128 rows x 2 halves (16B each)
    const int lr = tid >> 1;                 // 0..127
    const int lh = tid & 1;                  // 0..1
    const uint32_t sdst = (uint32_t)(lr * 48 + lh * 16);
    const size_t srow = (size_t)lr * 128;

    // issue chunk c into ring buffer (c & 3)
    #define ISSUE(c) do {                                                    \
        uint32_t sb_ = smb + (uint32_t)((c) & 3) * STAGEB;                   \
        cp16(sb_ + sdst,         Asrc + srow + (c) * 2 + lh);                \
        cp16(sb_ + TILEB + sdst, Wsrc + srow + (c) * 2 + lh);                \
    } while (0)

    ISSUE(0); asm volatile("cp.async.commit_group;" ::: "memory");
    ISSUE(1); asm volatile("cp.async.commit_group;" ::: "memory");
    ISSUE(2); asm volatile("cp.async.commit_group;" ::: "memory");

    #pragma unroll 1
    for (int c = 0; c < 64; c++) {
        asm volatile("cp.async.wait_group 2;" ::: "memory");
        __syncthreads();                     // chunk c visible to all warps

        if (c + 3 < 64) ISSUE(c + 3);        // into buf (c-1)&3: safe, all
                                             // warps finished chunk c-1
        asm volatile("cp.async.commit_group;" ::: "memory");  // uniform counts

        const uint32_t sbase = smb + (uint32_t)(c & 3) * STAGEB;
        uint32_t ah[2][4];
        ldm4(ah[0], sbase + aoff[0]);
        ldm4(ah[1], sbase + aoff[1]);

        #pragma unroll
        for (int p = 0; p < 4; p++) {
            uint32_t bh[4];
            ldm4(bh, sbase + TILEB + boff[p]);
            #pragma unroll
            for (int half = 0; half < 2; half++) {
                const int nt = 2 * p + half;
                const uint32_t b0 = bh[2 * half], b1 = bh[2 * half + 1];
                #pragma unroll
                for (int mt = 0; mt < 2; mt++)
                    mma_f16(acc[mt][nt], ah[mt], b0, b1);
            }
        }
    }
    #undef ISSUE

    if (mode == 0) {
        float* dst = (blockIdx.z == 0) ? g_Q : (blockIdx.z == 1 ? g_K : g_V);
        #pragma unroll
        for (int mt = 0; mt < 2; mt++) {
            #pragma unroll
            for (int fr = 0; fr < 2; fr++) {
                int m = rowBase + wm * 32 + mt * 16 + G + fr * 8;
                int b = m >> 11, n = m & 2047;
                size_t rb = ((size_t)(b << 4)) * SEQ;
                #pragma unroll
                for (int nt = 0; nt < 8; nt++) {
                    #pragma unroll
                    for (int fc = 0; fc < 2; fc++) {
                        int cc = colBase + wn * 64 + nt * 8 + 2 * T + fc;
                        int h = cc & 15, dd = cc >> 4;
                        dst[(((rb + (size_t)h * SEQ + n)) << 6) + dd] =
                            acc[mt][nt][fr * 2 + fc];
                    }
                }
            }
        }
    } else {
        #pragma unroll
        for (int mt = 0; mt < 2; mt++) {
            #pragma unroll
            for (int fr = 0; fr < 2; fr++) {
                int m = rowBase + wm * 32 + mt * 16 + G + fr * 8;
                float* op = out + (size_t)m * DMODEL + colBase + wn * 64;
                #pragma unroll
                for (int nt = 0; nt < 8; nt++)
                    *(float2*)&op[nt * 8 + 2 * T] =
                        make_float2(acc[mt][nt][fr * 2], acc[mt][nt][fr * 2 + 1]);
            }
        }
    }
}

// ===========================================================================
// Flash attention: fp16 S + fp16 PV (R10/R15 core unchanged); output written
// as packed fp16 into g_Ch4 (same element layout; identical rounding to what
// the O-proj loader previously applied).
// ===========================================================================
#define ATTN_SMEM ((64*36 + 32*72) * 4)   // 18432 B

__global__ __launch_bounds__(128) void attn_tc()
{
    extern __shared__ uint32_t smu[];
    uint32_t* Ks = smu;                 // [64][36] half2 k-pairs
    uint32_t* Vp = smu + 64 * 36;       // [32][72] half2 k-pairs

    const int tid  = threadIdx.x;
    const int w    = tid >> 5;
    const int lane = tid & 31;
    const int G    = lane >> 2;
    const int T    = lane & 3;
    const int bh   = blockIdx.y;        // 0..31
    const int qB   = blockIdx.x * 64;

    const float* Qg = g_Q + (size_t)bh * SEQ * HDIM;
    const float* Kg = g_K + (size_t)bh * SEQ * HDIM;
    const float* Vg = g_V + (size_t)bh * SEQ * HDIM;

    uint32_t qa[4][4];
    {
        const float sc = 0.125f;
        const int rlo = qB + w * 16 + G;
        const float* q0 = Qg + (size_t)rlo * 64;
        const float* q1 = Qg + (size_t)(rlo + 8) * 64;
        #pragma unroll
        for (int kc = 0; kc < 4; kc++) {
            int k = kc * 16 + 2 * T;
            qa[kc][0] = ph2(q0[k] * sc,     q0[k + 1] * sc);
            qa[kc][1] = ph2(q1[k] * sc,     q1[k + 1] * sc);
            qa[kc][2] = ph2(q0[k + 8] * sc, q0[k + 9] * sc);
            qa[kc][3] = ph2(q1[k + 8] * sc, q1[k + 9] * sc);
        }
    }

    float o[8][4];
    #pragma unroll
    for (int nt = 0; nt < 8; nt++)
        #pragma unroll
        for (int q = 0; q < 4; q++) o[nt][q] = 0.f;
    float m_lo = -1e30f, m_hi = -1e30f, l_lo = 0.f, l_hi = 0.f;

    #pragma unroll 1
    for (int t = 0; t < SEQ / 64; t++) {
        __syncthreads();
        const float* Kt = Kg + (size_t)t * 64 * HDIM;
        const float* Vt = Vg + (size_t)t * 64 * HDIM;
        #pragma unroll
        for (int i = 0; i < 8; i++) {
            int f = tid + i * 128;
            int r = f >> 4;
            int c4 = (f & 15) << 2;
            float4 kv = *(const float4*)(Kt + r * 64 + c4);
            *(uint2*)&Ks[r * 36 + (c4 >> 1)] =
                make_uint2(ph2(kv.x, kv.y), ph2(kv.z, kv.w));
        }
        #pragma unroll
        for (int i = 0; i < 4; i++) {
            int f = tid + i * 128;
            int kp = f >> 4;
            int c4 = (f & 15) << 2;
            float4 v0 = *(const float4*)(Vt + (2 * kp) * 64 + c4);
            float4 v1 = *(const float4*)(Vt + (2 * kp + 1) * 64 + c4);
            *(uint4*)&Vp[kp * 72 + c4] =
                make_uint4(ph2(v0.x, v1.x), ph2(v0.y, v1.y),
                           ph2(v0.z, v1.z), ph2(v0.w, v1.w));
        }
        __syncthreads();

        float s[8][4];
        #pragma unroll
        for (int nt = 0; nt < 8; nt++)
            #pragma unroll
            for (int q = 0; q < 4; q++) s[nt][q] = 0.f;
        #pragma unroll
        for (int kc = 0; kc < 4; kc++) {
            #pragma unroll
            for (int nt = 0; nt < 8; nt++) {
                const uint32_t* kr = &Ks[(nt * 8 + G) * 36 + kc * 8 + T];
                mma_f16(s[nt], qa[kc], kr[0], kr[4]);
            }
        }

        float tmx_lo = -1e30f, tmx_hi = -1e30f;
        #pragma unroll
        for (int nt = 0; nt < 8; nt++) {
            tmx_lo = fmaxf(tmx_lo, fmaxf(s[nt][0], s[nt][1]));
            tmx_hi = fmaxf(tmx_hi, fmaxf(s[nt][2], s[nt][3]));
        }
        #pragma unroll
        for (int off = 1; off <= 2; off <<= 1) {
            tmx_lo = fmaxf(tmx_lo, __shfl_xor_sync(0xffffffffu, tmx_lo, off));
            tmx_hi = fmaxf(tmx_hi, __shfl_xor_sync(0xffffffffu, tmx_hi, off));
        }
        float nm_lo = fmaxf(m_lo, tmx_lo), nm_hi = fmaxf(m_hi, tmx_hi);
        float corr_lo = __expf(m_lo - nm_lo), corr_hi = __expf(m_hi - nm_hi);
        m_lo = nm_lo; m_hi = nm_hi;
        float sum_lo = 0.f, sum_hi = 0.f;
        #pragma unroll
        for (int nt = 0; nt < 8; nt++) {
            s[nt][0] = __expf(s[nt][0] - nm_lo);
            s[nt][1] = __expf(s[nt][1] - nm_lo);
            s[nt][2] = __expf(s[nt][2] - nm_hi);
            s[nt][3] = __expf(s[nt][3] - nm_hi);
            sum_lo += s[nt][0] + s[nt][1];
            sum_hi += s[nt][2] + s[nt][3];
            o[nt][0] *= corr_lo; o[nt][1] *= corr_lo;
            o[nt][2] *= corr_hi; o[nt][3] *= corr_hi;
        }
        #pragma unroll
        for (int off = 1; off <= 2; off <<= 1) {
            sum_lo += __shfl_xor_sync(0xffffffffu, sum_lo, off);
            sum_hi += __shfl_xor_sync(0xffffffffu, sum_hi, off);
        }
        l_lo = l_lo * corr_lo + sum_lo;
        l_hi = l_hi * corr_hi + sum_hi;

        #pragma unroll
        for (int kc = 0; kc < 4; kc++) {
            uint32_t pa[4];
            pa[0] = ph2(s[2 * kc][0],     s[2 * kc][1]);
            pa[1] = ph2(s[2 * kc][2],     s[2 * kc][3]);
            pa[2] = ph2(s[2 * kc + 1][0], s[2 * kc + 1][1]);
            pa[3] = ph2(s[2 * kc + 1][2], s[2 * kc + 1][3]);
            #pragma unroll
            for (int nt = 0; nt < 8; nt++) {
                int col = nt * 8 + G;
                uint32_t b0 = Vp[(8 * kc + T) * 72 + col];
                uint32_t b1 = Vp[(8 * kc + 4 + T) * 72 + col];
                mma_f16(o[nt], pa, b0, b1);
            }
        }
    }

    // normalize + write fp16 concat: Ch[b*SEQ+n][h*64+dd] (packed half2)
    __half* Ch = (__half*)g_Ch4;
    const int b = bh >> 4, h = bh & 15;
    const int row_lo = qB + w * 16 + G;
    const float il_lo = 1.0f / l_lo, il_hi = 1.0f / l_hi;
    size_t base_lo = ((size_t)(b * SEQ + row_lo)) * DMODEL + h * 64;
    size_t base_hi = base_lo + (size_t)8 * DMODEL;
    #pragma unroll
    for (int nt = 0; nt < 8; nt++) {
        *(uint32_t*)&Ch[base_lo + nt * 8 + 2 * T] =
            ph2(o[nt][0] * il_lo, o[nt][1] * il_lo);
        *(uint32_t*)&Ch[base_hi + nt * 8 + 2 * T] =
            ph2(o[nt][2] * il_hi, o[nt][3] * il_hi);
    }
}

extern "C" void kernel_launch(void* const* d_in, const int* in_sizes, int n_in,
                              void* d_out, int out_size)
{
    const float* x  = (const float*)d_in[0];
    const float* wq = (const float*)d_in[1];
    const float* wk = (const float*)d_in[2];
    const float* wv = (const float*)d_in[3];
    const float* wo = (const float*)d_in[4];
    float* out = (float*)d_out;

    cudaFuncSetAttribute(gemm_f16a,
                         cudaFuncAttributeMaxDynamicSharedMemorySize, GEMM_SMEM);
    cudaFuncSetAttribute(attn_tc,
                         cudaFuncAttributeMaxDynamicSharedMemorySize, ATTN_SMEM);

    // 0) fp16-convert x + weights (once)
    prep<<<4096, 256>>>(x, wq, wk, wv, wo);

    // 1) QKV projections (fp16 cp.async pipeline) + head-split scatter
    gemm_f16a<<<dim3(DMODEL/128, MROWS/128, 3), 256, GEMM_SMEM>>>(nullptr, 0);

    // 2) Flash attention (fp16 S + fp16 PV) -> fp16 concat
    attn_tc<<<dim3(SEQ/64, BSZ*NHEAD), 128, ATTN_SMEM>>>();

    // 3) Output projection -> d_out (fp32)
    gemm_f16a<<<dim3(DMODEL/128, MROWS/128, 1), 256, GEMM_SMEM>>>(out, 1);
}